// round 5
// baseline (speedup 1.0000x reference)
#include <cuda_runtime.h>
#include <math.h>

#define T_TOK 2048
#define HDIM  2560
#define NEXP  8
#define ITXT  1536
#define IIMG  512
#define ISH   3072

// ---------------- scratch (static device globals; no allocs allowed) ----------
__device__ int   d_count[16];                 // 8 text + 8 image expert counts
__device__ int   d_slot_tok[16][T_TOK];       // token*2 + k  (k = rank within top2)
__device__ float d_slot_wt [16][T_TOK];       // renormalized routing weight
__device__ float d_h_text[(size_t)NEXP * T_TOK * ITXT];   // 96 MB
__device__ float d_h_img [(size_t)NEXP * T_TOK * IIMG];   // 32 MB
__device__ float d_mid_sh[(size_t)T_TOK * ISH];           // 25 MB
__device__ float d_ytok  [(size_t)T_TOK * 2 * HDIM];      // 40 MB

// ---------------- helpers ----------------------------------------------------
__device__ __forceinline__ float to_tf32(float x) {
    unsigned u;
    asm("cvt.rna.tf32.f32 %0, %1;" : "=r"(u) : "f"(x));
    return __uint_as_float(u);
}

__device__ __forceinline__ void mma_tf32(float c[4], const unsigned a[4],
                                         unsigned b0, unsigned b1) {
    asm volatile(
        "mma.sync.aligned.m16n8k8.row.col.f32.tf32.tf32.f32 "
        "{%0,%1,%2,%3}, {%4,%5,%6,%7}, {%8,%9}, {%0,%1,%2,%3};"
        : "+f"(c[0]), "+f"(c[1]), "+f"(c[2]), "+f"(c[3])
        : "r"(a[0]), "r"(a[1]), "r"(a[2]), "r"(a[3]), "r"(b0), "r"(b1));
}

// ---------------- init --------------------------------------------------------
__global__ void zero_counts_kernel() {
    if (threadIdx.x < 16) d_count[threadIdx.x] = 0;
}

// ---------------- routing -----------------------------------------------------
// One block per token, 8 warps: warp e computes logit of expert e for the
// token's modality; thread 0 does softmax + top2 + renorm + compaction.
// NOTE: visual_token_mask is a bool array promoted to int32 by the harness.
__global__ void route_kernel(const float* __restrict__ x,
                             const int* __restrict__ vmask,
                             const float* __restrict__ tgate,
                             const float* __restrict__ igate) {
    int t = blockIdx.x;
    int wid = threadIdx.x >> 5, lane = threadIdx.x & 31;
    bool vis = vmask[t] != 0;
    const float* gw = (vis ? igate : tgate) + (size_t)wid * HDIM;
    const float* xr = x + (size_t)t * HDIM;
    float s = 0.f;
    for (int i = lane; i < HDIM; i += 32) s += xr[i] * gw[i];
#pragma unroll
    for (int o = 16; o; o >>= 1) s += __shfl_xor_sync(0xffffffffu, s, o);
    __shared__ float logit[NEXP];
    if (lane == 0) logit[wid] = s;
    __syncthreads();
    if (threadIdx.x == 0) {
        float mx = logit[0];
#pragma unroll
        for (int e = 1; e < NEXP; e++) mx = fmaxf(mx, logit[e]);
        float p[NEXP];
#pragma unroll
        for (int e = 0; e < NEXP; e++) p[e] = expf(logit[e] - mx);
        int i0 = 0;
#pragma unroll
        for (int e = 1; e < NEXP; e++) if (p[e] > p[i0]) i0 = e;
        int i1 = (i0 == 0) ? 1 : 0;
#pragma unroll
        for (int e = 0; e < NEXP; e++)
            if (e != i0 && p[e] > p[i1]) i1 = e;
        float denom = p[i0] + p[i1];
        float w0 = p[i0] / denom;
        float w1 = p[i1] / denom;
        int base = vis ? 8 : 0;
        int g0 = base + i0;
        int g1 = base + i1;
        int pos0 = atomicAdd(&d_count[g0], 1);
        d_slot_tok[g0][pos0] = t * 2 + 0;
        d_slot_wt [g0][pos0] = w0;
        int pos1 = atomicAdd(&d_count[g1], 1);
        d_slot_tok[g1][pos1] = t * 2 + 1;
        d_slot_wt [g1][pos1] = w1;
    }
}

// ---------------- fused up-projection (G and U share A tile; SwiGLU) ---------
// C tile: BM=128 x BN=64, BK=32. 8 warps, warp tile 32x32 per matmul.
// mode: 0 = text experts (gather rows via slots), 1 = image experts, 2 = shared
__global__ __launch_bounds__(256)
void up_gemm(const float* __restrict__ X,
             const float* __restrict__ Wg_base,
             const float* __restrict__ Wu_base,
             int K, int N, int mode) {
    int e = blockIdx.z;
    const int* slot = nullptr;
    int M;
    float* hout;
    if (mode == 0) {
        M = d_count[e]; slot = d_slot_tok[e];
        hout = d_h_text + (size_t)e * T_TOK * N;
    } else if (mode == 1) {
        M = d_count[8 + e]; slot = d_slot_tok[8 + e];
        hout = d_h_img + (size_t)e * T_TOK * N;
    } else {
        M = T_TOK; hout = d_mid_sh;
    }
    int m0 = blockIdx.y * 128;
    if (m0 >= M) return;
    int n0 = blockIdx.x * 64;
    const float* Wg = Wg_base + (size_t)e * K * N;
    const float* Wu = Wu_base + (size_t)e * K * N;

    __shared__ float As[128][36];
    __shared__ float Bgs[32][72];
    __shared__ float Bus[32][72];
    __shared__ int   srcs[128];

    int tid = threadIdx.x;
    if (tid < 128) {
        int gr = m0 + tid;
        int s = -1;
        if (gr < M) s = slot ? (slot[gr] >> 1) : gr;
        srcs[tid] = s;
    }
    __syncthreads();

    float cg[2][4][4];
    float cu[2][4][4];
#pragma unroll
    for (int a = 0; a < 2; a++)
#pragma unroll
        for (int b = 0; b < 4; b++)
#pragma unroll
            for (int c = 0; c < 4; c++) { cg[a][b][c] = 0.f; cu[a][b][c] = 0.f; }

    int warp = tid >> 5, lane = tid & 31;
    int wm = warp >> 1, wn = warp & 1;

    int ar = tid >> 3;            // A loader: row 0..31 (stride 32), col (tid&7)*4
    int ac = (tid & 7) * 4;
    int bkr = tid >> 4;           // B loader: k-row 0..15 (stride 16), col (tid&15)*4
    int bc  = (tid & 15) * 4;

    int kiters = K >> 5;
    for (int kk = 0; kk < kiters; kk++) {
        int k0 = kk * 32;
        // A tile (with gather)
#pragma unroll
        for (int j = 0; j < 4; j++) {
            int r = ar + j * 32;
            int s = srcs[r];
            float4 v = make_float4(0.f, 0.f, 0.f, 0.f);
            if (s >= 0)
                v = *reinterpret_cast<const float4*>(X + (size_t)s * K + k0 + ac);
            float4 w;
            w.x = to_tf32(v.x); w.y = to_tf32(v.y);
            w.z = to_tf32(v.z); w.w = to_tf32(v.w);
            *reinterpret_cast<float4*>(&As[r][ac]) = w;
        }
        // B tiles (G and U)
#pragma unroll
        for (int j = 0; j < 2; j++) {
            int kr = bkr + j * 16;
            float4 vg = *reinterpret_cast<const float4*>(Wg + (size_t)(k0 + kr) * N + n0 + bc);
            float4 vu = *reinterpret_cast<const float4*>(Wu + (size_t)(k0 + kr) * N + n0 + bc);
            float4 wg4, wu4;
            wg4.x = to_tf32(vg.x); wg4.y = to_tf32(vg.y); wg4.z = to_tf32(vg.z); wg4.w = to_tf32(vg.w);
            wu4.x = to_tf32(vu.x); wu4.y = to_tf32(vu.y); wu4.z = to_tf32(vu.z); wu4.w = to_tf32(vu.w);
            *reinterpret_cast<float4*>(&Bgs[kr][bc]) = wg4;
            *reinterpret_cast<float4*>(&Bus[kr][bc]) = wu4;
        }
        __syncthreads();

#pragma unroll
        for (int kt = 0; kt < 4; kt++) {
            int kb = kt * 8;
            unsigned a[2][4];
            int r0 = wm * 32 + (lane >> 2);
            int c0 = kb + (lane & 3);
#pragma unroll
            for (int fm = 0; fm < 2; fm++) {
                int rr = r0 + fm * 16;
                a[fm][0] = __float_as_uint(As[rr][c0]);
                a[fm][1] = __float_as_uint(As[rr + 8][c0]);
                a[fm][2] = __float_as_uint(As[rr][c0 + 4]);
                a[fm][3] = __float_as_uint(As[rr + 8][c0 + 4]);
            }
#pragma unroll
            for (int fn = 0; fn < 4; fn++) {
                int bcc = wn * 32 + fn * 8 + (lane >> 2);
                int brr = kb + (lane & 3);
                unsigned bg0 = __float_as_uint(Bgs[brr][bcc]);
                unsigned bg1 = __float_as_uint(Bgs[brr + 4][bcc]);
                unsigned bu0 = __float_as_uint(Bus[brr][bcc]);
                unsigned bu1 = __float_as_uint(Bus[brr + 4][bcc]);
#pragma unroll
                for (int fm = 0; fm < 2; fm++) {
                    mma_tf32(cg[fm][fn], a[fm], bg0, bg1);
                    mma_tf32(cu[fm][fn], a[fm], bu0, bu1);
                }
            }
        }
        __syncthreads();
    }

    // epilogue: h = silu(g) * u
#pragma unroll
    for (int fm = 0; fm < 2; fm++) {
        int rbase = m0 + wm * 32 + fm * 16 + (lane >> 2);
#pragma unroll
        for (int fn = 0; fn < 4; fn++) {
            int col = n0 + wn * 32 + fn * 8 + (lane & 3) * 2;
#pragma unroll
            for (int half = 0; half < 2; half++) {
                int r = rbase + half * 8;
                if (r < M) {
                    float g0 = cg[fm][fn][half * 2 + 0];
                    float g1 = cg[fm][fn][half * 2 + 1];
                    float u0 = cu[fm][fn][half * 2 + 0];
                    float u1 = cu[fm][fn][half * 2 + 1];
                    float h0 = g0 / (1.f + expf(-g0)) * u0;
                    float h1 = g1 / (1.f + expf(-g1)) * u1;
                    *reinterpret_cast<float2*>(hout + (size_t)r * N + col) =
                        make_float2(h0, h1);
                }
            }
        }
    }
}

// ---------------- down-projection (optional scatter + per-row scale) ---------
// mode: 0 = text (A=h_text, C=y_tok scatter), 1 = image, 2 = shared (C=out)
__global__ __launch_bounds__(256)
void down_gemm(const float* __restrict__ Wd_base,
               float* __restrict__ outp,
               int K, int N, int mode) {
    int e = blockIdx.z;
    const float* A;
    const int* slot = nullptr;
    const float* wts = nullptr;
    int M;
    float* C;
    if (mode == 0) {
        M = d_count[e]; slot = d_slot_tok[e]; wts = d_slot_wt[e];
        A = d_h_text + (size_t)e * T_TOK * K; C = d_ytok;
    } else if (mode == 1) {
        M = d_count[8 + e]; slot = d_slot_tok[8 + e]; wts = d_slot_wt[8 + e];
        A = d_h_img + (size_t)e * T_TOK * K; C = d_ytok;
    } else {
        M = T_TOK; A = d_mid_sh; C = outp;
    }
    int m0 = blockIdx.y * 128;
    if (m0 >= M) return;
    int n0 = blockIdx.x * 64;
    const float* Wd = Wd_base + (size_t)e * K * N;

    __shared__ float As[128][36];
    __shared__ float Bs[32][72];

    int tid = threadIdx.x;
    float cc[2][4][4];
#pragma unroll
    for (int a = 0; a < 2; a++)
#pragma unroll
        for (int b = 0; b < 4; b++)
#pragma unroll
            for (int c = 0; c < 4; c++) cc[a][b][c] = 0.f;

    int warp = tid >> 5, lane = tid & 31;
    int wm = warp >> 1, wn = warp & 1;
    int ar = tid >> 3;
    int ac = (tid & 7) * 4;
    int bkr = tid >> 4;
    int bc  = (tid & 15) * 4;

    int kiters = K >> 5;
    for (int kk = 0; kk < kiters; kk++) {
        int k0 = kk * 32;
#pragma unroll
        for (int j = 0; j < 4; j++) {
            int r = ar + j * 32;
            int gr = m0 + r;
            float4 v = make_float4(0.f, 0.f, 0.f, 0.f);
            if (gr < M)
                v = *reinterpret_cast<const float4*>(A + (size_t)gr * K + k0 + ac);
            float4 w;
            w.x = to_tf32(v.x); w.y = to_tf32(v.y);
            w.z = to_tf32(v.z); w.w = to_tf32(v.w);
            *reinterpret_cast<float4*>(&As[r][ac]) = w;
        }
#pragma unroll
        for (int j = 0; j < 2; j++) {
            int kr = bkr + j * 16;
            float4 v = *reinterpret_cast<const float4*>(Wd + (size_t)(k0 + kr) * N + n0 + bc);
            float4 w;
            w.x = to_tf32(v.x); w.y = to_tf32(v.y);
            w.z = to_tf32(v.z); w.w = to_tf32(v.w);
            *reinterpret_cast<float4*>(&Bs[kr][bc]) = w;
        }
        __syncthreads();

#pragma unroll
        for (int kt = 0; kt < 4; kt++) {
            int kb = kt * 8;
            unsigned a[2][4];
            int r0 = wm * 32 + (lane >> 2);
            int c0 = kb + (lane & 3);
#pragma unroll
            for (int fm = 0; fm < 2; fm++) {
                int rr = r0 + fm * 16;
                a[fm][0] = __float_as_uint(As[rr][c0]);
                a[fm][1] = __float_as_uint(As[rr + 8][c0]);
                a[fm][2] = __float_as_uint(As[rr][c0 + 4]);
                a[fm][3] = __float_as_uint(As[rr + 8][c0 + 4]);
            }
#pragma unroll
            for (int fn = 0; fn < 4; fn++) {
                int bcc = wn * 32 + fn * 8 + (lane >> 2);
                int brr = kb + (lane & 3);
                unsigned b0 = __float_as_uint(Bs[brr][bcc]);
                unsigned b1 = __float_as_uint(Bs[brr + 4][bcc]);
#pragma unroll
                for (int fm = 0; fm < 2; fm++)
                    mma_tf32(cc[fm][fn], a[fm], b0, b1);
            }
        }
        __syncthreads();
    }

#pragma unroll
    for (int fm = 0; fm < 2; fm++) {
        int rbase = m0 + wm * 32 + fm * 16 + (lane >> 2);
#pragma unroll
        for (int fn = 0; fn < 4; fn++) {
            int col = n0 + wn * 32 + fn * 8 + (lane & 3) * 2;
#pragma unroll
            for (int half = 0; half < 2; half++) {
                int r = rbase + half * 8;
                if (r < M) {
                    int dst; float s;
                    if (slot) { dst = slot[r]; s = wts[r]; }
                    else      { dst = r;       s = 1.f; }
                    float v0 = s * cc[fm][fn][half * 2 + 0];
                    float v1 = s * cc[fm][fn][half * 2 + 1];
                    *reinterpret_cast<float2*>(C + (size_t)dst * N + col) =
                        make_float2(v0, v1);
                }
            }
        }
    }
}

// ---------------- final combine: out += y_tok[2t] + y_tok[2t+1] --------------
__global__ void combine_kernel(float* __restrict__ out) {
    int i = blockIdx.x * blockDim.x + threadIdx.x;   // float4 index
    const int total = T_TOK * HDIM / 4;
    if (i >= total) return;
    int row = i / (HDIM / 4);
    int c4 = i % (HDIM / 4);
    const float4* y0 = reinterpret_cast<const float4*>(d_ytok + (size_t)(2 * row) * HDIM) + c4;
    const float4* y1 = reinterpret_cast<const float4*>(d_ytok + (size_t)(2 * row + 1) * HDIM) + c4;
    float4 o = reinterpret_cast<float4*>(out)[i];
    float4 a = *y0, b = *y1;
    o.x += a.x + b.x; o.y += a.y + b.y;
    o.z += a.z + b.z; o.w += a.w + b.w;
    reinterpret_cast<float4*>(out)[i] = o;
}

// ---------------- launch ------------------------------------------------------
extern "C" void kernel_launch(void* const* d_in, const int* in_sizes, int n_in,
                              void* d_out, int out_size) {
    const float* x     = (const float*)d_in[0];
    const int*   vm    = (const int*)d_in[1];      // bool promoted to int32
    const float* tgate = (const float*)d_in[2];
    const float* twg   = (const float*)d_in[3];
    const float* twu   = (const float*)d_in[4];
    const float* twd   = (const float*)d_in[5];
    const float* igate = (const float*)d_in[6];
    const float* iwg   = (const float*)d_in[7];
    const float* iwu   = (const float*)d_in[8];
    const float* iwd   = (const float*)d_in[9];
    const float* shg   = (const float*)d_in[10];
    const float* shu   = (const float*)d_in[11];
    const float* shd   = (const float*)d_in[12];
    float* out = (float*)d_out;

    zero_counts_kernel<<<1, 32>>>();
    route_kernel<<<T_TOK, 256>>>(x, vm, tgate, igate);

    // up projections (fused SwiGLU)
    {
        dim3 g(ITXT / 64, T_TOK / 128, NEXP);
        up_gemm<<<g, 256>>>(x, twg, twu, HDIM, ITXT, 0);
    }
    {
        dim3 g(IIMG / 64, T_TOK / 128, NEXP);
        up_gemm<<<g, 256>>>(x, iwg, iwu, HDIM, IIMG, 1);
    }
    {
        dim3 g(ISH / 64, T_TOK / 128, 1);
        up_gemm<<<g, 256>>>(x, shg, shu, HDIM, ISH, 2);
    }

    // down projections
    {
        dim3 g(HDIM / 64, T_TOK / 128, 1);
        down_gemm<<<g, 256>>>(shd, out, ISH, HDIM, 2);   // writes base = shared_out
    }
    {
        dim3 g(HDIM / 64, T_TOK / 128, NEXP);
        down_gemm<<<g, 256>>>(twd, out, ITXT, HDIM, 0);  // scatters into y_tok
    }
    {
        dim3 g(HDIM / 64, T_TOK / 128, NEXP);
        down_gemm<<<g, 256>>>(iwd, out, IIMG, HDIM, 1);
    }

    // out += routed contributions
    {
        int total = T_TOK * HDIM / 4;
        combine_kernel<<<(total + 255) / 256, 256>>>(out);
    }
}

// round 6
// speedup vs baseline: 1.8650x; 1.8650x over previous
#include <cuda_runtime.h>
#include <math.h>

#define T_TOK 2048
#define HDIM  2560
#define NEXP  8
#define ITXT  1536
#define IIMG  512
#define ISH   3072

// ---------------- scratch (static device globals; no allocs allowed) ----------
__device__ int   d_count[16];                 // 8 text + 8 image expert counts
__device__ int   d_slot_tok[16][T_TOK];       // token*2 + k  (k = rank within top2)
__device__ float d_slot_wt [16][T_TOK];       // renormalized routing weight
__device__ float d_h_text[(size_t)NEXP * T_TOK * ITXT];   // 96 MB
__device__ float d_h_img [(size_t)NEXP * T_TOK * IIMG];   // 32 MB
__device__ float d_mid_sh[(size_t)T_TOK * ISH];           // 25 MB
__device__ float d_ytok  [(size_t)T_TOK * 2 * HDIM];      // 40 MB

// ---------------- helpers ----------------------------------------------------
__device__ __forceinline__ unsigned ld_tf32(const float* p) {
    unsigned u;
    asm("cvt.rna.tf32.f32 %0, %1;" : "=r"(u) : "f"(*p));
    return u;
}

__device__ __forceinline__ void mma_tf32(float c[4], const unsigned a[4],
                                         unsigned b0, unsigned b1) {
    asm volatile(
        "mma.sync.aligned.m16n8k8.row.col.f32.tf32.tf32.f32 "
        "{%0,%1,%2,%3}, {%4,%5,%6,%7}, {%8,%9}, {%0,%1,%2,%3};"
        : "+f"(c[0]), "+f"(c[1]), "+f"(c[2]), "+f"(c[3])
        : "r"(a[0]), "r"(a[1]), "r"(a[2]), "r"(a[3]), "r"(b0), "r"(b1));
}

__device__ __forceinline__ void cp16(void* smem, const void* g, int sz) {
    unsigned s = (unsigned)__cvta_generic_to_shared(smem);
    asm volatile("cp.async.cg.shared.global [%0], [%1], 16, %2;"
                 :: "r"(s), "l"(g), "r"(sz));
}
__device__ __forceinline__ void cp_commit() {
    asm volatile("cp.async.commit_group;");
}
template <int N> __device__ __forceinline__ void cp_wait() {
    asm volatile("cp.async.wait_group %0;" :: "n"(N));
}

// ---------------- init --------------------------------------------------------
__global__ void zero_counts_kernel() {
    if (threadIdx.x < 16) d_count[threadIdx.x] = 0;
}

// ---------------- routing -----------------------------------------------------
// visual_token_mask is bool in the reference -> promoted to int32 by the harness.
__global__ void route_kernel(const float* __restrict__ x,
                             const int* __restrict__ vmask,
                             const float* __restrict__ tgate,
                             const float* __restrict__ igate) {
    int t = blockIdx.x;
    int wid = threadIdx.x >> 5, lane = threadIdx.x & 31;
    bool vis = vmask[t] != 0;
    const float* gw = (vis ? igate : tgate) + (size_t)wid * HDIM;
    const float* xr = x + (size_t)t * HDIM;
    float s = 0.f;
    for (int i = lane; i < HDIM; i += 32) s += xr[i] * gw[i];
#pragma unroll
    for (int o = 16; o; o >>= 1) s += __shfl_xor_sync(0xffffffffu, s, o);
    __shared__ float logit[NEXP];
    if (lane == 0) logit[wid] = s;
    __syncthreads();
    if (threadIdx.x == 0) {
        float mx = logit[0];
#pragma unroll
        for (int e = 1; e < NEXP; e++) mx = fmaxf(mx, logit[e]);
        float p[NEXP];
#pragma unroll
        for (int e = 0; e < NEXP; e++) p[e] = expf(logit[e] - mx);
        int i0 = 0;
#pragma unroll
        for (int e = 1; e < NEXP; e++) if (p[e] > p[i0]) i0 = e;
        int i1 = (i0 == 0) ? 1 : 0;
#pragma unroll
        for (int e = 0; e < NEXP; e++)
            if (e != i0 && p[e] > p[i1]) i1 = e;
        float denom = p[i0] + p[i1];
        float w0 = p[i0] / denom;
        float w1 = p[i1] / denom;
        int base = vis ? 8 : 0;
        int g0 = base + i0;
        int g1 = base + i1;
        int pos0 = atomicAdd(&d_count[g0], 1);
        d_slot_tok[g0][pos0] = t * 2 + 0;
        d_slot_wt [g0][pos0] = w0;
        int pos1 = atomicAdd(&d_count[g1], 1);
        d_slot_tok[g1][pos1] = t * 2 + 1;
        d_slot_wt [g1][pos1] = w1;
    }
}

// ---------------- smem structs ------------------------------------------------
struct UpSmem {
    float As[2][128][36];
    float Bg[2][32][72];
    float Bu[2][32][72];
    int   srcs[128];
};
struct DownSmem {
    float As[2][128][36];
    float Bs[2][32][72];
};

// ---------------- fused up-projection (cp.async double-buffered) --------------
// C tile 128x64, BK=32, 8 warps (4m x 2n), warp tile 32x32, dual GEMM + SwiGLU.
__global__ __launch_bounds__(256)
void up_gemm(const float* __restrict__ X,
             const float* __restrict__ Wg_base,
             const float* __restrict__ Wu_base,
             int K, int N, int mode) {
    extern __shared__ char smem_raw[];
    UpSmem* sm = reinterpret_cast<UpSmem*>(smem_raw);

    int e = blockIdx.z;
    const int* slot = nullptr;
    int M;
    float* hout;
    if (mode == 0) {
        M = d_count[e]; slot = d_slot_tok[e];
        hout = d_h_text + (size_t)e * T_TOK * N;
    } else if (mode == 1) {
        M = d_count[8 + e]; slot = d_slot_tok[8 + e];
        hout = d_h_img + (size_t)e * T_TOK * N;
    } else {
        M = T_TOK; hout = d_mid_sh;
    }
    int m0 = blockIdx.y * 128;
    if (m0 >= M) return;
    int n0 = blockIdx.x * 64;
    const float* Wg = Wg_base + (size_t)e * K * N;
    const float* Wu = Wu_base + (size_t)e * K * N;

    int tid = threadIdx.x;
    if (tid < 128) {
        int gr = m0 + tid;
        int s = -1;
        if (gr < M) s = slot ? (slot[gr] >> 1) : gr;
        sm->srcs[tid] = s;
    }
    __syncthreads();

    int warp = tid >> 5, lane = tid & 31;
    int wm = warp >> 1, wn = warp & 1;
    int ar = tid >> 3;            // A loader rows 0..31 (stride 32)
    int ac = (tid & 7) * 4;
    int bkr = tid >> 4;           // B loader k-rows 0..15 (stride 16)
    int bc  = (tid & 15) * 4;

    // cache gather sources in registers (stable across k)
    int asrc[4];
#pragma unroll
    for (int j = 0; j < 4; j++) asrc[j] = sm->srcs[ar + j * 32];

    float cg[2][4][4];
    float cu[2][4][4];
#pragma unroll
    for (int a = 0; a < 2; a++)
#pragma unroll
        for (int b = 0; b < 4; b++)
#pragma unroll
            for (int c = 0; c < 4; c++) { cg[a][b][c] = 0.f; cu[a][b][c] = 0.f; }

    auto load_tile = [&](int kk, int st) {
        int k0 = kk * 32;
#pragma unroll
        for (int j = 0; j < 4; j++) {
            int r = ar + j * 32;
            int s = asrc[j];
            cp16(&sm->As[st][r][ac],
                 X + (size_t)(s >= 0 ? s : 0) * K + k0 + ac,
                 s >= 0 ? 16 : 0);
        }
#pragma unroll
        for (int j = 0; j < 2; j++) {
            int kr = bkr + j * 16;
            cp16(&sm->Bg[st][kr][bc], Wg + (size_t)(k0 + kr) * N + n0 + bc, 16);
            cp16(&sm->Bu[st][kr][bc], Wu + (size_t)(k0 + kr) * N + n0 + bc, 16);
        }
        cp_commit();
    };

    int kiters = K >> 5;
    load_tile(0, 0);

    for (int kk = 0; kk < kiters; kk++) {
        int st = kk & 1;
        if (kk + 1 < kiters) {
            load_tile(kk + 1, st ^ 1);
            cp_wait<1>();
        } else {
            cp_wait<0>();
        }
        __syncthreads();

        const float (*A)[36]  = sm->As[st];
        const float (*Bg2)[72] = sm->Bg[st];
        const float (*Bu2)[72] = sm->Bu[st];

#pragma unroll
        for (int kt = 0; kt < 4; kt++) {
            int kb = kt * 8;
            unsigned a[2][4];
            int r0 = wm * 32 + (lane >> 2);
            int c0 = kb + (lane & 3);
#pragma unroll
            for (int fm = 0; fm < 2; fm++) {
                int rr = r0 + fm * 16;
                a[fm][0] = ld_tf32(&A[rr][c0]);
                a[fm][1] = ld_tf32(&A[rr + 8][c0]);
                a[fm][2] = ld_tf32(&A[rr][c0 + 4]);
                a[fm][3] = ld_tf32(&A[rr + 8][c0 + 4]);
            }
#pragma unroll
            for (int fn = 0; fn < 4; fn++) {
                int bcc = wn * 32 + fn * 8 + (lane >> 2);
                int brr = kb + (lane & 3);
                unsigned bg0 = ld_tf32(&Bg2[brr][bcc]);
                unsigned bg1 = ld_tf32(&Bg2[brr + 4][bcc]);
                unsigned bu0 = ld_tf32(&Bu2[brr][bcc]);
                unsigned bu1 = ld_tf32(&Bu2[brr + 4][bcc]);
#pragma unroll
                for (int fm = 0; fm < 2; fm++) {
                    mma_tf32(cg[fm][fn], a[fm], bg0, bg1);
                    mma_tf32(cu[fm][fn], a[fm], bu0, bu1);
                }
            }
        }
        __syncthreads();
    }

    // epilogue: h = silu(g) * u
#pragma unroll
    for (int fm = 0; fm < 2; fm++) {
        int rbase = m0 + wm * 32 + fm * 16 + (lane >> 2);
#pragma unroll
        for (int fn = 0; fn < 4; fn++) {
            int col = n0 + wn * 32 + fn * 8 + (lane & 3) * 2;
#pragma unroll
            for (int half = 0; half < 2; half++) {
                int r = rbase + half * 8;
                if (r < M) {
                    float g0 = cg[fm][fn][half * 2 + 0];
                    float g1 = cg[fm][fn][half * 2 + 1];
                    float u0 = cu[fm][fn][half * 2 + 0];
                    float u1 = cu[fm][fn][half * 2 + 1];
                    float h0 = g0 / (1.f + expf(-g0)) * u0;
                    float h1 = g1 / (1.f + expf(-g1)) * u1;
                    *reinterpret_cast<float2*>(hout + (size_t)r * N + col) =
                        make_float2(h0, h1);
                }
            }
        }
    }
}

// ---------------- down-projection (cp.async double-buffered) ------------------
// mode: 0 = text (scatter to y_tok, scale), 1 = image, 2 = shared (write out)
__global__ __launch_bounds__(256)
void down_gemm(const float* __restrict__ Wd_base,
               float* __restrict__ outp,
               int K, int N, int mode) {
    extern __shared__ char smem_raw[];
    DownSmem* sm = reinterpret_cast<DownSmem*>(smem_raw);

    int e = blockIdx.z;
    const float* A;
    const int* slot = nullptr;
    const float* wts = nullptr;
    int M;
    float* C;
    if (mode == 0) {
        M = d_count[e]; slot = d_slot_tok[e]; wts = d_slot_wt[e];
        A = d_h_text + (size_t)e * T_TOK * K; C = d_ytok;
    } else if (mode == 1) {
        M = d_count[8 + e]; slot = d_slot_tok[8 + e]; wts = d_slot_wt[8 + e];
        A = d_h_img + (size_t)e * T_TOK * K; C = d_ytok;
    } else {
        M = T_TOK; A = d_mid_sh; C = outp;
    }
    int m0 = blockIdx.y * 128;
    if (m0 >= M) return;
    int n0 = blockIdx.x * 64;
    const float* Wd = Wd_base + (size_t)e * K * N;

    int tid = threadIdx.x;
    int warp = tid >> 5, lane = tid & 31;
    int wm = warp >> 1, wn = warp & 1;
    int ar = tid >> 3;
    int ac = (tid & 7) * 4;
    int bkr = tid >> 4;
    int bc  = (tid & 15) * 4;

    float cc[2][4][4];
#pragma unroll
    for (int a = 0; a < 2; a++)
#pragma unroll
        for (int b = 0; b < 4; b++)
#pragma unroll
            for (int c = 0; c < 4; c++) cc[a][b][c] = 0.f;

    auto load_tile = [&](int kk, int st) {
        int k0 = kk * 32;
#pragma unroll
        for (int j = 0; j < 4; j++) {
            int r = ar + j * 32;
            int gr = m0 + r;
            cp16(&sm->As[st][r][ac],
                 A + (size_t)(gr < M ? gr : 0) * K + k0 + ac,
                 gr < M ? 16 : 0);
        }
#pragma unroll
        for (int j = 0; j < 2; j++) {
            int kr = bkr + j * 16;
            cp16(&sm->Bs[st][kr][bc], Wd + (size_t)(k0 + kr) * N + n0 + bc, 16);
        }
        cp_commit();
    };

    int kiters = K >> 5;
    load_tile(0, 0);

    for (int kk = 0; kk < kiters; kk++) {
        int st = kk & 1;
        if (kk + 1 < kiters) {
            load_tile(kk + 1, st ^ 1);
            cp_wait<1>();
        } else {
            cp_wait<0>();
        }
        __syncthreads();

        const float (*As2)[36] = sm->As[st];
        const float (*Bs2)[72] = sm->Bs[st];

#pragma unroll
        for (int kt = 0; kt < 4; kt++) {
            int kb = kt * 8;
            unsigned a[2][4];
            int r0 = wm * 32 + (lane >> 2);
            int c0 = kb + (lane & 3);
#pragma unroll
            for (int fm = 0; fm < 2; fm++) {
                int rr = r0 + fm * 16;
                a[fm][0] = ld_tf32(&As2[rr][c0]);
                a[fm][1] = ld_tf32(&As2[rr + 8][c0]);
                a[fm][2] = ld_tf32(&As2[rr][c0 + 4]);
                a[fm][3] = ld_tf32(&As2[rr + 8][c0 + 4]);
            }
#pragma unroll
            for (int fn = 0; fn < 4; fn++) {
                int bcc = wn * 32 + fn * 8 + (lane >> 2);
                int brr = kb + (lane & 3);
                unsigned b0 = ld_tf32(&Bs2[brr][bcc]);
                unsigned b1 = ld_tf32(&Bs2[brr + 4][bcc]);
#pragma unroll
                for (int fm = 0; fm < 2; fm++)
                    mma_tf32(cc[fm][fn], a[fm], b0, b1);
            }
        }
        __syncthreads();
    }

#pragma unroll
    for (int fm = 0; fm < 2; fm++) {
        int rbase = m0 + wm * 32 + fm * 16 + (lane >> 2);
#pragma unroll
        for (int fn = 0; fn < 4; fn++) {
            int col = n0 + wn * 32 + fn * 8 + (lane & 3) * 2;
#pragma unroll
            for (int half = 0; half < 2; half++) {
                int r = rbase + half * 8;
                if (r < M) {
                    int dst; float s;
                    if (slot) { dst = slot[r]; s = wts[r]; }
                    else      { dst = r;       s = 1.f; }
                    float v0 = s * cc[fm][fn][half * 2 + 0];
                    float v1 = s * cc[fm][fn][half * 2 + 1];
                    *reinterpret_cast<float2*>(C + (size_t)dst * N + col) =
                        make_float2(v0, v1);
                }
            }
        }
    }
}

// ---------------- final combine: out += y_tok[2t] + y_tok[2t+1] --------------
__global__ void combine_kernel(float* __restrict__ out) {
    int i = blockIdx.x * blockDim.x + threadIdx.x;   // float4 index
    const int total = T_TOK * HDIM / 4;
    if (i >= total) return;
    int row = i / (HDIM / 4);
    int c4 = i % (HDIM / 4);
    const float4* y0 = reinterpret_cast<const float4*>(d_ytok + (size_t)(2 * row) * HDIM) + c4;
    const float4* y1 = reinterpret_cast<const float4*>(d_ytok + (size_t)(2 * row + 1) * HDIM) + c4;
    float4 o = reinterpret_cast<float4*>(out)[i];
    float4 a = *y0, b = *y1;
    o.x += a.x + b.x; o.y += a.y + b.y;
    o.z += a.z + b.z; o.w += a.w + b.w;
    reinterpret_cast<float4*>(out)[i] = o;
}

// ---------------- launch ------------------------------------------------------
extern "C" void kernel_launch(void* const* d_in, const int* in_sizes, int n_in,
                              void* d_out, int out_size) {
    const float* x     = (const float*)d_in[0];
    const int*   vm    = (const int*)d_in[1];      // bool promoted to int32
    const float* tgate = (const float*)d_in[2];
    const float* twg   = (const float*)d_in[3];
    const float* twu   = (const float*)d_in[4];
    const float* twd   = (const float*)d_in[5];
    const float* igate = (const float*)d_in[6];
    const float* iwg   = (const float*)d_in[7];
    const float* iwu   = (const float*)d_in[8];
    const float* iwd   = (const float*)d_in[9];
    const float* shg   = (const float*)d_in[10];
    const float* shu   = (const float*)d_in[11];
    const float* shd   = (const float*)d_in[12];
    float* out = (float*)d_out;

    const int UP_SMEM   = (int)sizeof(UpSmem);
    const int DOWN_SMEM = (int)sizeof(DownSmem);
    static bool attr_set = false;
    if (!attr_set) {
        cudaFuncSetAttribute(up_gemm,
            cudaFuncAttributeMaxDynamicSharedMemorySize, UP_SMEM);
        cudaFuncSetAttribute(down_gemm,
            cudaFuncAttributeMaxDynamicSharedMemorySize, DOWN_SMEM);
        attr_set = true;
    }

    zero_counts_kernel<<<1, 32>>>();
    route_kernel<<<T_TOK, 256>>>(x, vm, tgate, igate);

    // up projections (fused SwiGLU)
    {
        dim3 g(ITXT / 64, T_TOK / 128, NEXP);
        up_gemm<<<g, 256, UP_SMEM>>>(x, twg, twu, HDIM, ITXT, 0);
    }
    {
        dim3 g(IIMG / 64, T_TOK / 128, NEXP);
        up_gemm<<<g, 256, UP_SMEM>>>(x, iwg, iwu, HDIM, IIMG, 1);
    }
    {
        dim3 g(ISH / 64, T_TOK / 128, 1);
        up_gemm<<<g, 256, UP_SMEM>>>(x, shg, shu, HDIM, ISH, 2);
    }

    // down projections
    {
        dim3 g(HDIM / 64, T_TOK / 128, 1);
        down_gemm<<<g, 256, DOWN_SMEM>>>(shd, out, ISH, HDIM, 2);   // shared_out
    }
    {
        dim3 g(HDIM / 64, T_TOK / 128, NEXP);
        down_gemm<<<g, 256, DOWN_SMEM>>>(twd, out, ITXT, HDIM, 0);  // -> y_tok
    }
    {
        dim3 g(HDIM / 64, T_TOK / 128, NEXP);
        down_gemm<<<g, 256, DOWN_SMEM>>>(iwd, out, IIMG, HDIM, 1);  // -> y_tok
    }

    // out += routed contributions
    {
        int total = T_TOK * HDIM / 4;
        combine_kernel<<<(total + 255) / 256, 256>>>(out);
    }
}

// round 7
// speedup vs baseline: 2.2769x; 1.2208x over previous
#include <cuda_runtime.h>
#include <math.h>

#define T_TOK 2048
#define HDIM  2560
#define NEXP  8
#define ITXT  1536
#define IIMG  512
#define ISH   3072

// ---------------- scratch (static device globals; no allocs allowed) ----------
__device__ int   d_count[16];
__device__ int   d_slot_tok[16][T_TOK];
__device__ float d_slot_wt [16][T_TOK];
__device__ float d_x32 [(size_t)T_TOK * HDIM];             // pre-rounded X (tf32)
__device__ float d_h_text[(size_t)NEXP * T_TOK * ITXT];
__device__ float d_h_img [(size_t)NEXP * T_TOK * IIMG];
__device__ float d_mid_sh[(size_t)T_TOK * ISH];
__device__ float d_ytok  [(size_t)T_TOK * 2 * HDIM];

// ---------------- helpers ----------------------------------------------------
__device__ __forceinline__ unsigned ld_tf32(const float* p) {
    unsigned u;
    asm("cvt.rna.tf32.f32 %0, %1;" : "=r"(u) : "f"(*p));
    return u;
}
__device__ __forceinline__ float rnd_tf32(float x) {
    unsigned u;
    asm("cvt.rna.tf32.f32 %0, %1;" : "=r"(u) : "f"(x));
    return __uint_as_float(u);
}

__device__ __forceinline__ void mma_tf32(float c[4], const unsigned a[4],
                                         unsigned b0, unsigned b1) {
    asm volatile(
        "mma.sync.aligned.m16n8k8.row.col.f32.tf32.tf32.f32 "
        "{%0,%1,%2,%3}, {%4,%5,%6,%7}, {%8,%9}, {%0,%1,%2,%3};"
        : "+f"(c[0]), "+f"(c[1]), "+f"(c[2]), "+f"(c[3])
        : "r"(a[0]), "r"(a[1]), "r"(a[2]), "r"(a[3]), "r"(b0), "r"(b1));
}

__device__ __forceinline__ void cp16(void* smem, const void* g, int sz) {
    unsigned s = (unsigned)__cvta_generic_to_shared(smem);
    asm volatile("cp.async.cg.shared.global [%0], [%1], 16, %2;"
                 :: "r"(s), "l"(g), "r"(sz));
}
__device__ __forceinline__ void cp_commit() {
    asm volatile("cp.async.commit_group;");
}
template <int N> __device__ __forceinline__ void cp_wait() {
    asm volatile("cp.async.wait_group %0;" :: "n"(N));
}

// ---------------- init / pre-round -------------------------------------------
__global__ void zero_counts_kernel() {
    if (threadIdx.x < 16) d_count[threadIdx.x] = 0;
}

__global__ void preround_x_kernel(const float* __restrict__ x) {
    int i = blockIdx.x * blockDim.x + threadIdx.x;
    const int total = T_TOK * HDIM / 4;
    if (i >= total) return;
    float4 v = reinterpret_cast<const float4*>(x)[i];
    float4 w;
    w.x = rnd_tf32(v.x); w.y = rnd_tf32(v.y);
    w.z = rnd_tf32(v.z); w.w = rnd_tf32(v.w);
    reinterpret_cast<float4*>(d_x32)[i] = w;
}

// ---------------- routing -----------------------------------------------------
// visual_token_mask is bool in the reference -> promoted to int32 by the harness.
__global__ void route_kernel(const float* __restrict__ x,
                             const int* __restrict__ vmask,
                             const float* __restrict__ tgate,
                             const float* __restrict__ igate) {
    int t = blockIdx.x;
    int wid = threadIdx.x >> 5, lane = threadIdx.x & 31;
    bool vis = vmask[t] != 0;
    const float* gw = (vis ? igate : tgate) + (size_t)wid * HDIM;
    const float* xr = x + (size_t)t * HDIM;
    float s = 0.f;
    for (int i = lane; i < HDIM; i += 32) s += xr[i] * gw[i];
#pragma unroll
    for (int o = 16; o; o >>= 1) s += __shfl_xor_sync(0xffffffffu, s, o);
    __shared__ float logit[NEXP];
    if (lane == 0) logit[wid] = s;
    __syncthreads();
    if (threadIdx.x == 0) {
        float mx = logit[0];
#pragma unroll
        for (int e = 1; e < NEXP; e++) mx = fmaxf(mx, logit[e]);
        float p[NEXP];
#pragma unroll
        for (int e = 0; e < NEXP; e++) p[e] = expf(logit[e] - mx);
        int i0 = 0;
#pragma unroll
        for (int e = 1; e < NEXP; e++) if (p[e] > p[i0]) i0 = e;
        int i1 = (i0 == 0) ? 1 : 0;
#pragma unroll
        for (int e = 0; e < NEXP; e++)
            if (e != i0 && p[e] > p[i1]) i1 = e;
        float denom = p[i0] + p[i1];
        float w0 = p[i0] / denom;
        float w1 = p[i1] / denom;
        int base = vis ? 8 : 0;
        int g0 = base + i0;
        int g1 = base + i1;
        int pos0 = atomicAdd(&d_count[g0], 1);
        d_slot_tok[g0][pos0] = t * 2 + 0;
        d_slot_wt [g0][pos0] = w0;
        int pos1 = atomicAdd(&d_count[g1], 1);
        d_slot_tok[g1][pos1] = t * 2 + 1;
        d_slot_wt [g1][pos1] = w1;
    }
}

// ---------------- smem structs (3-stage) --------------------------------------
struct UpSmem {
    float As[3][128][36];
    float Bg[3][32][72];
    float Bu[3][32][72];
    int   srcs[128];
};
struct DownSmem {
    float As[3][128][36];
    float Bs[3][32][72];
};

// ---------------- fused up-projection (3-stage cp.async, 1 barrier/ktile) -----
// C tile 128x64, BK=32, 8 warps (4m x 2n), dual GEMM + SwiGLU.
// A comes from pre-rounded d_x32 -> no cvt on A path.
__global__ __launch_bounds__(256)
void up_gemm(const float* __restrict__ Wg_base,
             const float* __restrict__ Wu_base,
             int K, int N, int mode) {
    extern __shared__ char smem_raw[];
    UpSmem* sm = reinterpret_cast<UpSmem*>(smem_raw);

    int e = blockIdx.z;
    const int* slot = nullptr;
    int M;
    float* hout;
    if (mode == 0) {
        M = d_count[e]; slot = d_slot_tok[e];
        hout = d_h_text + (size_t)e * T_TOK * N;
    } else if (mode == 1) {
        M = d_count[8 + e]; slot = d_slot_tok[8 + e];
        hout = d_h_img + (size_t)e * T_TOK * N;
    } else {
        M = T_TOK; hout = d_mid_sh;
    }
    int m0 = blockIdx.y * 128;
    if (m0 >= M) return;
    int n0 = blockIdx.x * 64;
    const float* X  = d_x32;
    const float* Wg = Wg_base + (size_t)e * K * N;
    const float* Wu = Wu_base + (size_t)e * K * N;

    int tid = threadIdx.x;
    if (tid < 128) {
        int gr = m0 + tid;
        int s = -1;
        if (gr < M) s = slot ? (slot[gr] >> 1) : gr;
        sm->srcs[tid] = s;
    }
    __syncthreads();

    int warp = tid >> 5, lane = tid & 31;
    int wm = warp >> 1, wn = warp & 1;
    int ar = tid >> 3;            // A loader rows 0..31 (stride 32)
    int ac = (tid & 7) * 4;
    int bkr = tid >> 4;           // B loader k-rows 0..15 (stride 16)
    int bc  = (tid & 15) * 4;

    int asrc[4];
#pragma unroll
    for (int j = 0; j < 4; j++) asrc[j] = sm->srcs[ar + j * 32];

    float cg[2][4][4];
    float cu[2][4][4];
#pragma unroll
    for (int a = 0; a < 2; a++)
#pragma unroll
        for (int b = 0; b < 4; b++)
#pragma unroll
            for (int c = 0; c < 4; c++) { cg[a][b][c] = 0.f; cu[a][b][c] = 0.f; }

    auto load_tile = [&](int kk, int st) {
        int k0 = kk * 32;
#pragma unroll
        for (int j = 0; j < 4; j++) {
            int r = ar + j * 32;
            int s = asrc[j];
            cp16(&sm->As[st][r][ac],
                 X + (size_t)(s >= 0 ? s : 0) * K + k0 + ac,
                 s >= 0 ? 16 : 0);
        }
#pragma unroll
        for (int j = 0; j < 2; j++) {
            int kr = bkr + j * 16;
            cp16(&sm->Bg[st][kr][bc], Wg + (size_t)(k0 + kr) * N + n0 + bc, 16);
            cp16(&sm->Bu[st][kr][bc], Wu + (size_t)(k0 + kr) * N + n0 + bc, 16);
        }
        cp_commit();
    };

    int kiters = K >> 5;
    load_tile(0, 0);
    load_tile(1, 1);

    for (int kk = 0; kk < kiters; kk++) {
        int st = kk % 3;
        if (kk < kiters - 1) cp_wait<1>(); else cp_wait<0>();
        __syncthreads();
        if (kk + 2 < kiters) load_tile(kk + 2, (kk + 2) % 3);

        const float (*A)[36]   = sm->As[st];
        const float (*Bg2)[72] = sm->Bg[st];
        const float (*Bu2)[72] = sm->Bu[st];

#pragma unroll
        for (int kt = 0; kt < 4; kt++) {
            int kb = kt * 8;
            unsigned a[2][4];
            int r0 = wm * 32 + (lane >> 2);
            int c0 = kb + (lane & 3);
#pragma unroll
            for (int fm = 0; fm < 2; fm++) {
                int rr = r0 + fm * 16;
                a[fm][0] = __float_as_uint(A[rr][c0]);
                a[fm][1] = __float_as_uint(A[rr + 8][c0]);
                a[fm][2] = __float_as_uint(A[rr][c0 + 4]);
                a[fm][3] = __float_as_uint(A[rr + 8][c0 + 4]);
            }
#pragma unroll
            for (int fn = 0; fn < 4; fn++) {
                int bcc = wn * 32 + fn * 8 + (lane >> 2);
                int brr = kb + (lane & 3);
                unsigned bg0 = ld_tf32(&Bg2[brr][bcc]);
                unsigned bg1 = ld_tf32(&Bg2[brr + 4][bcc]);
                unsigned bu0 = ld_tf32(&Bu2[brr][bcc]);
                unsigned bu1 = ld_tf32(&Bu2[brr + 4][bcc]);
#pragma unroll
                for (int fm = 0; fm < 2; fm++) {
                    mma_tf32(cg[fm][fn], a[fm], bg0, bg1);
                    mma_tf32(cu[fm][fn], a[fm], bu0, bu1);
                }
            }
        }
    }

    // epilogue: h = round_tf32(silu(g) * u)  (pre-rounded for the down GEMM)
#pragma unroll
    for (int fm = 0; fm < 2; fm++) {
        int rbase = m0 + wm * 32 + fm * 16 + (lane >> 2);
#pragma unroll
        for (int fn = 0; fn < 4; fn++) {
            int col = n0 + wn * 32 + fn * 8 + (lane & 3) * 2;
#pragma unroll
            for (int half = 0; half < 2; half++) {
                int r = rbase + half * 8;
                if (r < M) {
                    float g0 = cg[fm][fn][half * 2 + 0];
                    float g1 = cg[fm][fn][half * 2 + 1];
                    float u0 = cu[fm][fn][half * 2 + 0];
                    float u1 = cu[fm][fn][half * 2 + 1];
                    float h0 = rnd_tf32(g0 / (1.f + expf(-g0)) * u0);
                    float h1 = rnd_tf32(g1 / (1.f + expf(-g1)) * u1);
                    *reinterpret_cast<float2*>(hout + (size_t)r * N + col) =
                        make_float2(h0, h1);
                }
            }
        }
    }
}

// ---------------- down-projection (3-stage cp.async) --------------------------
// A (h / mid) is pre-rounded -> no cvt on A path.
__global__ __launch_bounds__(256)
void down_gemm(const float* __restrict__ Wd_base,
               float* __restrict__ outp,
               int K, int N, int mode) {
    extern __shared__ char smem_raw[];
    DownSmem* sm = reinterpret_cast<DownSmem*>(smem_raw);

    int e = blockIdx.z;
    const float* A;
    const int* slot = nullptr;
    const float* wts = nullptr;
    int M;
    float* C;
    if (mode == 0) {
        M = d_count[e]; slot = d_slot_tok[e]; wts = d_slot_wt[e];
        A = d_h_text + (size_t)e * T_TOK * K; C = d_ytok;
    } else if (mode == 1) {
        M = d_count[8 + e]; slot = d_slot_tok[8 + e]; wts = d_slot_wt[8 + e];
        A = d_h_img + (size_t)e * T_TOK * K; C = d_ytok;
    } else {
        M = T_TOK; A = d_mid_sh; C = outp;
    }
    int m0 = blockIdx.y * 128;
    if (m0 >= M) return;
    int n0 = blockIdx.x * 64;
    const float* Wd = Wd_base + (size_t)e * K * N;

    int tid = threadIdx.x;
    int warp = tid >> 5, lane = tid & 31;
    int wm = warp >> 1, wn = warp & 1;
    int ar = tid >> 3;
    int ac = (tid & 7) * 4;
    int bkr = tid >> 4;
    int bc  = (tid & 15) * 4;

    float cc[2][4][4];
#pragma unroll
    for (int a = 0; a < 2; a++)
#pragma unroll
        for (int b = 0; b < 4; b++)
#pragma unroll
            for (int c = 0; c < 4; c++) cc[a][b][c] = 0.f;

    auto load_tile = [&](int kk, int st) {
        int k0 = kk * 32;
#pragma unroll
        for (int j = 0; j < 4; j++) {
            int r = ar + j * 32;
            int gr = m0 + r;
            cp16(&sm->As[st][r][ac],
                 A + (size_t)(gr < M ? gr : 0) * K + k0 + ac,
                 gr < M ? 16 : 0);
        }
#pragma unroll
        for (int j = 0; j < 2; j++) {
            int kr = bkr + j * 16;
            cp16(&sm->Bs[st][kr][bc], Wd + (size_t)(k0 + kr) * N + n0 + bc, 16);
        }
        cp_commit();
    };

    int kiters = K >> 5;
    load_tile(0, 0);
    load_tile(1, 1);

    for (int kk = 0; kk < kiters; kk++) {
        int st = kk % 3;
        if (kk < kiters - 1) cp_wait<1>(); else cp_wait<0>();
        __syncthreads();
        if (kk + 2 < kiters) load_tile(kk + 2, (kk + 2) % 3);

        const float (*As2)[36] = sm->As[st];
        const float (*Bs2)[72] = sm->Bs[st];

#pragma unroll
        for (int kt = 0; kt < 4; kt++) {
            int kb = kt * 8;
            unsigned a[2][4];
            int r0 = wm * 32 + (lane >> 2);
            int c0 = kb + (lane & 3);
#pragma unroll
            for (int fm = 0; fm < 2; fm++) {
                int rr = r0 + fm * 16;
                a[fm][0] = __float_as_uint(As2[rr][c0]);
                a[fm][1] = __float_as_uint(As2[rr + 8][c0]);
                a[fm][2] = __float_as_uint(As2[rr][c0 + 4]);
                a[fm][3] = __float_as_uint(As2[rr + 8][c0 + 4]);
            }
#pragma unroll
            for (int fn = 0; fn < 4; fn++) {
                int bcc = wn * 32 + fn * 8 + (lane >> 2);
                int brr = kb + (lane & 3);
                unsigned b0 = ld_tf32(&Bs2[brr][bcc]);
                unsigned b1 = ld_tf32(&Bs2[brr + 4][bcc]);
#pragma unroll
                for (int fm = 0; fm < 2; fm++)
                    mma_tf32(cc[fm][fn], a[fm], b0, b1);
            }
        }
    }

#pragma unroll
    for (int fm = 0; fm < 2; fm++) {
        int rbase = m0 + wm * 32 + fm * 16 + (lane >> 2);
#pragma unroll
        for (int fn = 0; fn < 4; fn++) {
            int col = n0 + wn * 32 + fn * 8 + (lane & 3) * 2;
#pragma unroll
            for (int half = 0; half < 2; half++) {
                int r = rbase + half * 8;
                if (r < M) {
                    int dst; float s;
                    if (slot) { dst = slot[r]; s = wts[r]; }
                    else      { dst = r;       s = 1.f; }
                    float v0 = s * cc[fm][fn][half * 2 + 0];
                    float v1 = s * cc[fm][fn][half * 2 + 1];
                    *reinterpret_cast<float2*>(C + (size_t)dst * N + col) =
                        make_float2(v0, v1);
                }
            }
        }
    }
}

// ---------------- final combine: out += y_tok[2t] + y_tok[2t+1] --------------
__global__ void combine_kernel(float* __restrict__ out) {
    int i = blockIdx.x * blockDim.x + threadIdx.x;
    const int total = T_TOK * HDIM / 4;
    if (i >= total) return;
    int row = i / (HDIM / 4);
    int c4 = i % (HDIM / 4);
    const float4* y0 = reinterpret_cast<const float4*>(d_ytok + (size_t)(2 * row) * HDIM) + c4;
    const float4* y1 = reinterpret_cast<const float4*>(d_ytok + (size_t)(2 * row + 1) * HDIM) + c4;
    float4 o = reinterpret_cast<float4*>(out)[i];
    float4 a = *y0, b = *y1;
    o.x += a.x + b.x; o.y += a.y + b.y;
    o.z += a.z + b.z; o.w += a.w + b.w;
    reinterpret_cast<float4*>(out)[i] = o;
}

// ---------------- launch ------------------------------------------------------
extern "C" void kernel_launch(void* const* d_in, const int* in_sizes, int n_in,
                              void* d_out, int out_size) {
    const float* x     = (const float*)d_in[0];
    const int*   vm    = (const int*)d_in[1];      // bool promoted to int32
    const float* tgate = (const float*)d_in[2];
    const float* twg   = (const float*)d_in[3];
    const float* twu   = (const float*)d_in[4];
    const float* twd   = (const float*)d_in[5];
    const float* igate = (const float*)d_in[6];
    const float* iwg   = (const float*)d_in[7];
    const float* iwu   = (const float*)d_in[8];
    const float* iwd   = (const float*)d_in[9];
    const float* shg   = (const float*)d_in[10];
    const float* shu   = (const float*)d_in[11];
    const float* shd   = (const float*)d_in[12];
    float* out = (float*)d_out;

    const int UP_SMEM   = (int)sizeof(UpSmem);
    const int DOWN_SMEM = (int)sizeof(DownSmem);

    static bool init = false;
    static cudaStream_t s1, s2;
    static cudaEvent_t evRoot, evRoute, evJ1, evJ2;
    if (!init) {
        cudaStreamCreateWithFlags(&s1, cudaStreamNonBlocking);
        cudaStreamCreateWithFlags(&s2, cudaStreamNonBlocking);
        cudaEventCreateWithFlags(&evRoot,  cudaEventDisableTiming);
        cudaEventCreateWithFlags(&evRoute, cudaEventDisableTiming);
        cudaEventCreateWithFlags(&evJ1,    cudaEventDisableTiming);
        cudaEventCreateWithFlags(&evJ2,    cudaEventDisableTiming);
        cudaFuncSetAttribute(up_gemm,
            cudaFuncAttributeMaxDynamicSharedMemorySize, UP_SMEM);
        cudaFuncSetAttribute(down_gemm,
            cudaFuncAttributeMaxDynamicSharedMemorySize, DOWN_SMEM);
        init = true;
    }

    cudaStream_t s0 = 0;   // captured legacy stream

    // prologue on s0
    zero_counts_kernel<<<1, 32, 0, s0>>>();
    {
        int total = T_TOK * HDIM / 4;
        preround_x_kernel<<<(total + 255) / 256, 256, 0, s0>>>(x);
    }
    cudaEventRecord(evRoot, s0);

    // s1: shared-expert chain (independent of routing)
    cudaStreamWaitEvent(s1, evRoot, 0);
    {
        dim3 g(ISH / 64, T_TOK / 128, 1);
        up_gemm<<<g, 256, UP_SMEM, s1>>>(shg, shu, HDIM, ISH, 2);
    }
    {
        dim3 g(HDIM / 64, T_TOK / 128, 1);
        down_gemm<<<g, 256, DOWN_SMEM, s1>>>(shd, out, ISH, HDIM, 2);
    }
    cudaEventRecord(evJ1, s1);

    // s0: routing, then text chain
    route_kernel<<<T_TOK, 256, 0, s0>>>(x, vm, tgate, igate);
    cudaEventRecord(evRoute, s0);

    // s2: image chain (needs routing)
    cudaStreamWaitEvent(s2, evRoute, 0);
    {
        dim3 g(IIMG / 64, T_TOK / 128, NEXP);
        up_gemm<<<g, 256, UP_SMEM, s2>>>(iwg, iwu, HDIM, IIMG, 1);
    }
    {
        dim3 g(HDIM / 64, T_TOK / 128, NEXP);
        down_gemm<<<g, 256, DOWN_SMEM, s2>>>(iwd, out, IIMG, HDIM, 1);
    }
    cudaEventRecord(evJ2, s2);

    // s0: text chain
    {
        dim3 g(ITXT / 64, T_TOK / 128, NEXP);
        up_gemm<<<g, 256, UP_SMEM, s0>>>(twg, twu, HDIM, ITXT, 0);
    }
    {
        dim3 g(HDIM / 64, T_TOK / 128, NEXP);
        down_gemm<<<g, 256, DOWN_SMEM, s0>>>(twd, out, ITXT, HDIM, 0);
    }

    // join + combine
    cudaStreamWaitEvent(s0, evJ1, 0);
    cudaStreamWaitEvent(s0, evJ2, 0);
    {
        int total = T_TOK * HDIM / 4;
        combine_kernel<<<(total + 255) / 256, 256, 0, s0>>>(out);
    }
}